// round 11
// baseline (speedup 1.0000x reference)
#include <cuda_runtime.h>
#include <math.h>

// Problem constants (B,C,H,W,K) = (32,8,64,64,16)
#define BATCH 32
#define CHW    (8 * 64 * 64)           // 32768 elements per batch
#define N_ELEM (BATCH * CHW)           // 1,048,576
#define KMIX   16
#define TPB    128
#define NBLK   (N_ELEM / TPB)          // 8192 logical tiles
#define NSM    148
#define GRID   (NSM * 12)              // persistent: one wave at 12 CTAs/SM

__global__ void init_sldj_kernel(const float* __restrict__ sldj_in,
                                 float* __restrict__ sldj_out) {
    int i = threadIdx.x;
    if (i < BATCH) sldj_out[i] = sldj_in[i];
}

__device__ __forceinline__ void prefetch_l2(const void* p) {
    asm volatile("prefetch.global.L2 [%0];" :: "l"(p));
}

// 12 CTAs/SM bucket (<=42 regs) — the empirically-best occupancy point (R5).
__global__ void __launch_bounds__(TPB, 12)
coupling_kernel(const float*  __restrict__ x_change,
                const float*  __restrict__ x_id,
                const float*  __restrict__ a,
                const float*  __restrict__ b,
                const float4* __restrict__ pi4,
                const float4* __restrict__ mu4,
                const float4* __restrict__ s4,
                float* __restrict__ out,       // [N_ELEM]
                float* __restrict__ out_id,    // [N_ELEM]
                float* __restrict__ sldj_out)  // [BATCH]
{
    const int tid  = threadIdx.x;
    const int lane = tid & 31;

    // Persistent grid-stride over logical tiles: one wave, no transitions.
    for (int blk = blockIdx.x; blk < NBLK; blk += GRID) {
        // ---- prefetch next tile's mixture data into L2 (register-free MLP) ----
        const int nxt = blk + GRID;
        if (nxt < NBLK) {
            const size_t off = (size_t)nxt * TPB * KMIX * 4 + (size_t)tid * 64;
            prefetch_l2((const char*)pi4 + off);
            prefetch_l2((const char*)mu4 + off);
            prefetch_l2((const char*)s4  + off);
        }

        const int i = blk * TPB + tid;

        // ---- streaming loads (single-use, evict-first) ----
        const float x = __ldcs(&x_change[i]);

        const int base4 = i * (KMIX / 4);   // float4 index, fully coalesced

        // Linear-domain mixture accumulation:
        //   e_k = exp(pi_k), es_k = exp(-s_k), z_k = (x-mu_k)*es_k
        //   t_k = exp(-z_k), sigma_k = 1/(1+t_k)
        //   S1 = sum e*sigma        (~ cdf * sum e)
        //   S0 = sum e*t*sigma      (~ (1-cdf)*sum e; S1+S0 == sum e exactly)
        //   P  = sum e*es*t*sigma^2 (~ pdf * sum e)
        float S1 = 0.0f, S0 = 0.0f, P = 0.0f;
#pragma unroll
        for (int j = 0; j < 4; j++) {
            const float4 p4 = __ldcs(&pi4[base4 + j]);
            const float4 m4 = __ldcs(&mu4[base4 + j]);
            const float4 t4 = __ldcs(&s4[base4 + j]);

            const float pk[4] = {p4.x, p4.y, p4.z, p4.w};
            const float mk[4] = {m4.x, m4.y, m4.z, m4.w};
            const float sk[4] = {t4.x, t4.y, t4.z, t4.w};
#pragma unroll
            for (int q = 0; q < 4; q++) {
                const float ep = __expf(pk[q]);
                const float es = __expf(-sk[q]);
                const float z  = (x - mk[q]) * es;
                const float t  = __expf(-z);
                const float rc = __fdividef(1.0f, 1.0f + t);
                const float r1 = ep * rc;
                const float rt = r1 * t;
                S1 += r1;
                S0 += rt;
                P  += rt * (es * rc);
            }
        }

        // epilogue-only inputs (short live ranges)
        const float av  = __ldcs(&a[i]);
        const float bv  = __ldcs(&b[i]);
        const float xid = __ldcs(&x_id[i]);

        const float lS1 = __logf(S1);
        const float lS0 = __logf(S0);
        const float lSe = __logf(S1 + S0);
        const float lP  = __logf(P);

        // out = (log(S1/S0) + b) * exp(a);  ldj = lP + lSe - lS1 - lS0 + a
        __stcs(&out[i],    (lS1 - lS0 + bv) * __expf(av));
        __stcs(&out_id[i], xid);

        // ---- warp-level ldj reduction, one fire-and-forget RED per warp ----
        float v = lP + lSe - lS1 - lS0 + av;
#pragma unroll
        for (int off = 16; off > 0; off >>= 1)
            v += __shfl_down_sync(0xFFFFFFFFu, v, off);
        if (lane == 0)
            atomicAdd(&sldj_out[blk >> 8], v);   // 256 tiles per batch
    }
}

extern "C" void kernel_launch(void* const* d_in, const int* in_sizes, int n_in,
                              void* d_out, int out_size) {
    // Inputs (metadata order): x_change, x_id, sldj, a, b, pi, mu, s
    const float* x_change = (const float*)d_in[0];
    const float* x_id     = (const float*)d_in[1];
    const float* sldj     = (const float*)d_in[2];
    const float* a        = (const float*)d_in[3];
    const float* b        = (const float*)d_in[4];
    const float4* pi4     = (const float4*)d_in[5];
    const float4* mu4     = (const float4*)d_in[6];
    const float4* s4      = (const float4*)d_in[7];

    float* out      = (float*)d_out;
    float* out_id   = out + N_ELEM;
    float* sldj_out = out + 2 * N_ELEM;

    init_sldj_kernel<<<1, 32>>>(sldj, sldj_out);
    coupling_kernel<<<GRID, TPB>>>(x_change, x_id, a, b,
                                   pi4, mu4, s4,
                                   out, out_id, sldj_out);
}